// round 2
// baseline (speedup 1.0000x reference)
#include <cuda_runtime.h>
#include <math.h>

// ---------------------------------------------------------------------------
// LSTM: N=64, T=1024, D=1024, H=1024. out[n][t][j] = h_t.
// Strategy (round 1, fp32 baseline):
//   1) xpose_kernel: x[n][t][d] -> g_xT[t][d][n]  (so the recurrent GEMM's
//      A-matrix is [k][n] row-major for both the x part and the h part).
//   2) lstm_kernel: persistent, 256 CTAs x 128 thr, custom grid barrier.
//      Per step t: preact[64 x 4096] = concat(x_t, h_{t-1})[64 x 2048] @ [Wx;Wh]
//      via 32 col-blocks x 8 K-splits -> partials -> barrier -> fused
//      reduce+gates+state update (c in registers) -> barrier.
// ---------------------------------------------------------------------------

namespace {
constexpr int NB   = 64;     // batch
constexpr int T    = 1024;
constexpr int D    = 1024;
constexpr int H    = 1024;
constexpr int G    = 4096;   // 4H
constexpr int NCTA = 256;
constexpr int KS   = 8;      // K-splits (K2 = 2048 -> 256 per CTA)
constexpr int CBW  = 128;    // gate-column block width (32 blocks)
}

// Scratch (device globals: no allocations allowed in kernel_launch)
__device__ float g_xT[(size_t)T * D * NB];   // 256 MB, [t][k][n]
__device__ float g_hT[H * NB];               // [j][n]  (h transposed)
__device__ float g_part[KS * NB * G];        // [ks][n][g] partial preacts, 8 MB
__device__ unsigned g_bar_count;
__device__ unsigned g_bar_epoch;

// ---------------------------------------------------------------------------
// Grid barrier (all CTAs guaranteed co-resident: 256 CTAs, 2/SM).
// ---------------------------------------------------------------------------
__device__ __forceinline__ void grid_barrier(unsigned nb, unsigned& ep) {
    __threadfence();
    __syncthreads();
    if (threadIdx.x == 0) {
        unsigned prev = atomicAdd(&g_bar_count, 1u);
        if (prev == nb - 1u) {
            g_bar_count = 0u;
            __threadfence();
            atomicExch(&g_bar_epoch, ep + 1u);
        } else {
            while (*((volatile unsigned*)&g_bar_epoch) == ep) {
                __nanosleep(64);
            }
        }
        __threadfence();
    }
    ep += 1u;
    __syncthreads();
}

// ---------------------------------------------------------------------------
// x[n][t][d] -> g_xT[t][d][n]
// block = (t, kb): 64x64 tile over (n, k). 256 threads.
// ---------------------------------------------------------------------------
__global__ void __launch_bounds__(256) xpose_kernel(const float* __restrict__ x) {
    __shared__ float s[64][68];
    const int t   = blockIdx.x;
    const int kb  = blockIdx.y << 6;
    const int tid = threadIdx.x;

#pragma unroll
    for (int p = 0; p < 4; ++p) {
        int id = p * 256 + tid;          // 0..1023 float4 tasks
        int n  = id >> 4;                // 0..63
        int k4 = (id & 15) << 2;         // 0..60
        float4 v = *reinterpret_cast<const float4*>(
            x + ((size_t)n * T + t) * D + kb + k4);
        *reinterpret_cast<float4*>(&s[n][k4]) = v;
    }
    __syncthreads();
#pragma unroll
    for (int p = 0; p < 4; ++p) {
        int id = p * 256 + tid;
        int n4 = (id & 15) << 2;         // output float4 along n
        int kk = id >> 4;                // 0..63
        float4 v = make_float4(s[n4 + 0][kk], s[n4 + 1][kk],
                               s[n4 + 2][kk], s[n4 + 3][kk]);
        *reinterpret_cast<float4*>(
            g_xT + ((size_t)t * D + kb + kk) * NB + n4) = v;
    }
}

// ---------------------------------------------------------------------------
// Persistent LSTM kernel.
// ---------------------------------------------------------------------------
__global__ void __launch_bounds__(128, 2) lstm_kernel(
    const float* __restrict__ h0, const float* __restrict__ Wx,
    const float* __restrict__ Wh, const float* __restrict__ b,
    float* __restrict__ out)
{
    __shared__ float sA[32][64];    // A tile [kk][n], 8 KB
    __shared__ float sW[32][128];   // W tile [kk][g], 16 KB

    const int tid = threadIdx.x;
    const int u   = blockIdx.x;
    const unsigned nb = gridDim.x;

    unsigned ep = *((volatile unsigned*)&g_bar_epoch);

    // ---- update-phase cell mapping: 2 cells per thread, same n ----
    const int cell0 = u * 256 + tid;     // 0..65407
    const int n_u   = cell0 >> 10;       // 0..63
    const int j_u   = cell0 & 1023;      // second cell is j_u + 128

    // init h state (transposed) and c state (registers)
    g_hT[(size_t)j_u * NB + n_u]         = h0[(size_t)n_u * H + j_u];
    g_hT[(size_t)(j_u + 128) * NB + n_u] = h0[(size_t)n_u * H + j_u + 128];
    float c0 = 0.f, c1 = 0.f;

    // ---- GEMM mapping: cb = column block, ks = K-split ----
    const int cb = u >> 3;               // 0..31
    const int ks = u & 7;                // 0..7
    const int k0 = ks * 256;
    const bool xpart = (ks < 4);
    const float* Wbase = xpart ? (Wx + (size_t)k0 * G)
                               : (Wh + (size_t)(k0 - 1024) * G);
    const float* Ah = g_hT + (size_t)(k0 >= 1024 ? (k0 - 1024) : 0) * NB;

    const int nq = tid >> 4;             // 0..7  -> rows nq*8
    const int gq = tid & 15;             // 0..15 -> cols gq*8

    grid_barrier(nb, ep);                // h0 in g_hT, g_xT ready (prev kernel)

    for (int t = 0; t < T; ++t) {
        // ================= GEMM phase =================
        const float* Abase = xpart ? (g_xT + ((size_t)t * D + k0) * NB) : Ah;

        float acc[8][8];
#pragma unroll
        for (int i = 0; i < 8; ++i)
#pragma unroll
            for (int j = 0; j < 8; ++j) acc[i][j] = 0.f;

        for (int cch = 0; cch < 8; ++cch) {
            __syncthreads();
            // load A tile 32x64 (coalesced float4)
#pragma unroll
            for (int p = 0; p < 4; ++p) {
                int id = p * 128 + tid;          // 0..511
                int kk = id >> 4;
                int n4 = (id & 15) << 2;
                float4 v = *reinterpret_cast<const float4*>(
                    Abase + (size_t)(cch * 32 + kk) * NB + n4);
                *reinterpret_cast<float4*>(&sA[kk][n4]) = v;
            }
            // load W tile 32x128 (coalesced float4)
#pragma unroll
            for (int p = 0; p < 8; ++p) {
                int id = p * 128 + tid;          // 0..1023
                int kk = id >> 5;
                int g4 = (id & 31) << 2;
                float4 v = *reinterpret_cast<const float4*>(
                    Wbase + (size_t)(cch * 32 + kk) * G + cb * CBW + g4);
                *reinterpret_cast<float4*>(&sW[kk][g4]) = v;
            }
            __syncthreads();

#pragma unroll 4
            for (int kk = 0; kk < 32; ++kk) {
                float a[8], w[8];
                *reinterpret_cast<float4*>(&a[0]) =
                    *reinterpret_cast<const float4*>(&sA[kk][nq * 8]);
                *reinterpret_cast<float4*>(&a[4]) =
                    *reinterpret_cast<const float4*>(&sA[kk][nq * 8 + 4]);
                *reinterpret_cast<float4*>(&w[0]) =
                    *reinterpret_cast<const float4*>(&sW[kk][gq * 8]);
                *reinterpret_cast<float4*>(&w[4]) =
                    *reinterpret_cast<const float4*>(&sW[kk][gq * 8 + 4]);
#pragma unroll
                for (int i = 0; i < 8; ++i)
#pragma unroll
                    for (int j = 0; j < 8; ++j)
                        acc[i][j] = fmaf(a[i], w[j], acc[i][j]);
            }
        }
        // write partials: g_part[ks][n][cb*128 + gq*8 + ...]
#pragma unroll
        for (int i = 0; i < 8; ++i) {
            int n = nq * 8 + i;
            float* dst = g_part + ((size_t)ks * NB + n) * G + cb * CBW + gq * 8;
            *reinterpret_cast<float4*>(dst) =
                make_float4(acc[i][0], acc[i][1], acc[i][2], acc[i][3]);
            *reinterpret_cast<float4*>(dst + 4) =
                make_float4(acc[i][4], acc[i][5], acc[i][6], acc[i][7]);
        }

        grid_barrier(nb, ep);

        // ================= update phase =================
        {
            float pa0[4], pa1[4];
#pragma unroll
            for (int g = 0; g < 4; ++g) {
                float s0 = b[g * H + j_u];
                float s1 = b[g * H + j_u + 128];
#pragma unroll
                for (int q = 0; q < KS; ++q) {
                    const float* pp =
                        g_part + ((size_t)q * NB + n_u) * G + g * H;
                    s0 += pp[j_u];
                    s1 += pp[j_u + 128];
                }
                pa0[g] = s0;
                pa1[g] = s1;
            }
            float i0 = 1.f / (1.f + expf(-pa0[0]));
            float f0 = 1.f / (1.f + expf(-pa0[1]));
            float o0 = 1.f / (1.f + expf(-pa0[2]));
            float q0 = tanhf(pa0[3]);
            c0 = f0 * c0 + i0 * q0;
            float hv0 = o0 * tanhf(c0);

            float i1 = 1.f / (1.f + expf(-pa1[0]));
            float f1 = 1.f / (1.f + expf(-pa1[1]));
            float o1 = 1.f / (1.f + expf(-pa1[2]));
            float q1 = tanhf(pa1[3]);
            c1 = f1 * c1 + i1 * q1;
            float hv1 = o1 * tanhf(c1);

            out[((size_t)n_u * T + t) * H + j_u]       = hv0;
            out[((size_t)n_u * T + t) * H + j_u + 128] = hv1;
            g_hT[(size_t)j_u * NB + n_u]               = hv0;
            g_hT[(size_t)(j_u + 128) * NB + n_u]       = hv1;
        }

        grid_barrier(nb, ep);
    }
}

// ---------------------------------------------------------------------------
extern "C" void kernel_launch(void* const* d_in, const int* in_sizes, int n_in,
                              void* d_out, int out_size) {
    (void)in_sizes; (void)n_in; (void)out_size;
    const float* x  = (const float*)d_in[0];
    const float* h0 = (const float*)d_in[1];
    const float* Wx = (const float*)d_in[2];
    const float* Wh = (const float*)d_in[3];
    const float* b  = (const float*)d_in[4];
    float* out = (float*)d_out;

    dim3 gT(T, D / 64);
    xpose_kernel<<<gT, 256>>>(x);
    lstm_kernel<<<NCTA, 128>>>(h0, Wx, Wh, b, out);
}

// round 3
// speedup vs baseline: 1.0005x; 1.0005x over previous
#include <cuda_runtime.h>
#include <math.h>

// ---------------------------------------------------------------------------
// LSTM: N=64, T=1024, D=1024, H=1024. out[n][t][j] = h_t.
// Strategy (round 1, fp32 baseline):
//   1) xpose_kernel: x[n][t][d] -> g_xT[t][d][n]  (so the recurrent GEMM's
//      A-matrix is [k][n] row-major for both the x part and the h part).
//   2) lstm_kernel: persistent, 256 CTAs x 128 thr, custom grid barrier.
//      Per step t: preact[64 x 4096] = concat(x_t, h_{t-1})[64 x 2048] @ [Wx;Wh]
//      via 32 col-blocks x 8 K-splits -> partials -> barrier -> fused
//      reduce+gates+state update (c in registers) -> barrier.
// ---------------------------------------------------------------------------

namespace {
constexpr int NB   = 64;     // batch
constexpr int T    = 1024;
constexpr int D    = 1024;
constexpr int H    = 1024;
constexpr int G    = 4096;   // 4H
constexpr int NCTA = 256;
constexpr int KS   = 8;      // K-splits (K2 = 2048 -> 256 per CTA)
constexpr int CBW  = 128;    // gate-column block width (32 blocks)
}

// Scratch (device globals: no allocations allowed in kernel_launch)
__device__ float g_xT[(size_t)T * D * NB];   // 256 MB, [t][k][n]
__device__ float g_hT[H * NB];               // [j][n]  (h transposed)
__device__ float g_part[KS * NB * G];        // [ks][n][g] partial preacts, 8 MB
__device__ unsigned g_bar_count;
__device__ unsigned g_bar_epoch;

// ---------------------------------------------------------------------------
// Grid barrier (all CTAs guaranteed co-resident: 256 CTAs, 2/SM).
// ---------------------------------------------------------------------------
__device__ __forceinline__ void grid_barrier(unsigned nb, unsigned& ep) {
    __threadfence();
    __syncthreads();
    if (threadIdx.x == 0) {
        unsigned prev = atomicAdd(&g_bar_count, 1u);
        if (prev == nb - 1u) {
            g_bar_count = 0u;
            __threadfence();
            atomicExch(&g_bar_epoch, ep + 1u);
        } else {
            while (*((volatile unsigned*)&g_bar_epoch) == ep) {
                __nanosleep(64);
            }
        }
        __threadfence();
    }
    ep += 1u;
    __syncthreads();
}

// ---------------------------------------------------------------------------
// x[n][t][d] -> g_xT[t][d][n]
// block = (t, kb): 64x64 tile over (n, k). 256 threads.
// ---------------------------------------------------------------------------
__global__ void __launch_bounds__(256) xpose_kernel(const float* __restrict__ x) {
    __shared__ float s[64][68];
    const int t   = blockIdx.x;
    const int kb  = blockIdx.y << 6;
    const int tid = threadIdx.x;

#pragma unroll
    for (int p = 0; p < 4; ++p) {
        int id = p * 256 + tid;          // 0..1023 float4 tasks
        int n  = id >> 4;                // 0..63
        int k4 = (id & 15) << 2;         // 0..60
        float4 v = *reinterpret_cast<const float4*>(
            x + ((size_t)n * T + t) * D + kb + k4);
        *reinterpret_cast<float4*>(&s[n][k4]) = v;
    }
    __syncthreads();
#pragma unroll
    for (int p = 0; p < 4; ++p) {
        int id = p * 256 + tid;
        int n4 = (id & 15) << 2;         // output float4 along n
        int kk = id >> 4;                // 0..63
        float4 v = make_float4(s[n4 + 0][kk], s[n4 + 1][kk],
                               s[n4 + 2][kk], s[n4 + 3][kk]);
        *reinterpret_cast<float4*>(
            g_xT + ((size_t)t * D + kb + kk) * NB + n4) = v;
    }
}

// ---------------------------------------------------------------------------
// Persistent LSTM kernel.
// ---------------------------------------------------------------------------
__global__ void __launch_bounds__(128, 2) lstm_kernel(
    const float* __restrict__ h0, const float* __restrict__ Wx,
    const float* __restrict__ Wh, const float* __restrict__ b,
    float* __restrict__ out)
{
    __shared__ float sA[32][64];    // A tile [kk][n], 8 KB
    __shared__ float sW[32][128];   // W tile [kk][g], 16 KB

    const int tid = threadIdx.x;
    const int u   = blockIdx.x;
    const unsigned nb = gridDim.x;

    unsigned ep = *((volatile unsigned*)&g_bar_epoch);

    // ---- update-phase cell mapping: 2 cells per thread, same n ----
    const int cell0 = u * 256 + tid;     // 0..65407
    const int n_u   = cell0 >> 10;       // 0..63
    const int j_u   = cell0 & 1023;      // second cell is j_u + 128

    // init h state (transposed) and c state (registers)
    g_hT[(size_t)j_u * NB + n_u]         = h0[(size_t)n_u * H + j_u];
    g_hT[(size_t)(j_u + 128) * NB + n_u] = h0[(size_t)n_u * H + j_u + 128];
    float c0 = 0.f, c1 = 0.f;

    // ---- GEMM mapping: cb = column block, ks = K-split ----
    const int cb = u >> 3;               // 0..31
    const int ks = u & 7;                // 0..7
    const int k0 = ks * 256;
    const bool xpart = (ks < 4);
    const float* Wbase = xpart ? (Wx + (size_t)k0 * G)
                               : (Wh + (size_t)(k0 - 1024) * G);
    const float* Ah = g_hT + (size_t)(k0 >= 1024 ? (k0 - 1024) : 0) * NB;

    const int nq = tid >> 4;             // 0..7  -> rows nq*8
    const int gq = tid & 15;             // 0..15 -> cols gq*8

    grid_barrier(nb, ep);                // h0 in g_hT, g_xT ready (prev kernel)

    for (int t = 0; t < T; ++t) {
        // ================= GEMM phase =================
        const float* Abase = xpart ? (g_xT + ((size_t)t * D + k0) * NB) : Ah;

        float acc[8][8];
#pragma unroll
        for (int i = 0; i < 8; ++i)
#pragma unroll
            for (int j = 0; j < 8; ++j) acc[i][j] = 0.f;

        for (int cch = 0; cch < 8; ++cch) {
            __syncthreads();
            // load A tile 32x64 (coalesced float4)
#pragma unroll
            for (int p = 0; p < 4; ++p) {
                int id = p * 128 + tid;          // 0..511
                int kk = id >> 4;
                int n4 = (id & 15) << 2;
                float4 v = *reinterpret_cast<const float4*>(
                    Abase + (size_t)(cch * 32 + kk) * NB + n4);
                *reinterpret_cast<float4*>(&sA[kk][n4]) = v;
            }
            // load W tile 32x128 (coalesced float4)
#pragma unroll
            for (int p = 0; p < 8; ++p) {
                int id = p * 128 + tid;          // 0..1023
                int kk = id >> 5;
                int g4 = (id & 31) << 2;
                float4 v = *reinterpret_cast<const float4*>(
                    Wbase + (size_t)(cch * 32 + kk) * G + cb * CBW + g4);
                *reinterpret_cast<float4*>(&sW[kk][g4]) = v;
            }
            __syncthreads();

#pragma unroll 4
            for (int kk = 0; kk < 32; ++kk) {
                float a[8], w[8];
                *reinterpret_cast<float4*>(&a[0]) =
                    *reinterpret_cast<const float4*>(&sA[kk][nq * 8]);
                *reinterpret_cast<float4*>(&a[4]) =
                    *reinterpret_cast<const float4*>(&sA[kk][nq * 8 + 4]);
                *reinterpret_cast<float4*>(&w[0]) =
                    *reinterpret_cast<const float4*>(&sW[kk][gq * 8]);
                *reinterpret_cast<float4*>(&w[4]) =
                    *reinterpret_cast<const float4*>(&sW[kk][gq * 8 + 4]);
#pragma unroll
                for (int i = 0; i < 8; ++i)
#pragma unroll
                    for (int j = 0; j < 8; ++j)
                        acc[i][j] = fmaf(a[i], w[j], acc[i][j]);
            }
        }
        // write partials: g_part[ks][n][cb*128 + gq*8 + ...]
#pragma unroll
        for (int i = 0; i < 8; ++i) {
            int n = nq * 8 + i;
            float* dst = g_part + ((size_t)ks * NB + n) * G + cb * CBW + gq * 8;
            *reinterpret_cast<float4*>(dst) =
                make_float4(acc[i][0], acc[i][1], acc[i][2], acc[i][3]);
            *reinterpret_cast<float4*>(dst + 4) =
                make_float4(acc[i][4], acc[i][5], acc[i][6], acc[i][7]);
        }

        grid_barrier(nb, ep);

        // ================= update phase =================
        {
            float pa0[4], pa1[4];
#pragma unroll
            for (int g = 0; g < 4; ++g) {
                float s0 = b[g * H + j_u];
                float s1 = b[g * H + j_u + 128];
#pragma unroll
                for (int q = 0; q < KS; ++q) {
                    const float* pp =
                        g_part + ((size_t)q * NB + n_u) * G + g * H;
                    s0 += pp[j_u];
                    s1 += pp[j_u + 128];
                }
                pa0[g] = s0;
                pa1[g] = s1;
            }
            float i0 = 1.f / (1.f + expf(-pa0[0]));
            float f0 = 1.f / (1.f + expf(-pa0[1]));
            float o0 = 1.f / (1.f + expf(-pa0[2]));
            float q0 = tanhf(pa0[3]);
            c0 = f0 * c0 + i0 * q0;
            float hv0 = o0 * tanhf(c0);

            float i1 = 1.f / (1.f + expf(-pa1[0]));
            float f1 = 1.f / (1.f + expf(-pa1[1]));
            float o1 = 1.f / (1.f + expf(-pa1[2]));
            float q1 = tanhf(pa1[3]);
            c1 = f1 * c1 + i1 * q1;
            float hv1 = o1 * tanhf(c1);

            out[((size_t)n_u * T + t) * H + j_u]       = hv0;
            out[((size_t)n_u * T + t) * H + j_u + 128] = hv1;
            g_hT[(size_t)j_u * NB + n_u]               = hv0;
            g_hT[(size_t)(j_u + 128) * NB + n_u]       = hv1;
        }

        grid_barrier(nb, ep);
    }
}

// ---------------------------------------------------------------------------
extern "C" void kernel_launch(void* const* d_in, const int* in_sizes, int n_in,
                              void* d_out, int out_size) {
    (void)in_sizes; (void)n_in; (void)out_size;
    const float* x  = (const float*)d_in[0];
    const float* h0 = (const float*)d_in[1];
    const float* Wx = (const float*)d_in[2];
    const float* Wh = (const float*)d_in[3];
    const float* b  = (const float*)d_in[4];
    float* out = (float*)d_out;

    dim3 gT(T, D / 64);
    xpose_kernel<<<gT, 256>>>(x);
    lstm_kernel<<<NCTA, 128>>>(h0, Wx, Wh, b, out);
}